// round 4
// baseline (speedup 1.0000x reference)
#include <cuda_runtime.h>
#include <math.h>

#define BATCH 4
#define SEQ   2048
#define VEC   512
#define HEADS 8
#define HEAD  64
#define ROWS  (BATCH*SEQ)          // 8192
#define SCALE 0.125f               // 1/sqrt(64)
#define LN_EPS 1e-3f

// Scratch (allocation-free rule: __device__ globals)
__device__ float g_Q[ROWS*VEC];
__device__ float g_K[ROWS*VEC];
__device__ float g_V[ROWS*VEC];
__device__ float g_X[ROWS*VEC];

// ---- packed f32x2 helpers (ptxas never auto-fuses these) --------------------
__device__ __forceinline__ void ffma2(unsigned long long& d,
                                      unsigned long long a,
                                      unsigned long long b) {
    asm("fma.rn.f32x2 %0, %1, %2, %0;" : "+l"(d) : "l"(a), "l"(b));
}
__device__ __forceinline__ unsigned long long dup2(float x) {
    unsigned long long r;
    asm("mov.b64 %0, {%1, %1};" : "=l"(r) : "f"(x));
    return r;
}
__device__ __forceinline__ float2 unpk(unsigned long long p) {
    float2 f;
    asm("mov.b64 {%0, %1}, %2;" : "=f"(f.x), "=f"(f.y) : "l"(p));
    return f;
}

// ---------------------------------------------------------------------------
// Projection: C[row, h*64+d] = sum_v A[row,v] * W[h,v,d]
// BM=128, BN=64 (one head), BK=32. 128 threads (16x8), 8x8 micro, FFMA2.
// ---------------------------------------------------------------------------
__global__ __launch_bounds__(128) void proj_kernel(const float* __restrict__ A,
                                                   const float* __restrict__ W,
                                                   int sel) {
    float* C = (sel == 0) ? g_Q : (sel == 1) ? g_K : g_V;

    __shared__ float As[32 * 128];   // [k][m]
    __shared__ float Ws[32 * 64];    // [k][n]

    const int h  = blockIdx.y;
    const int r0 = blockIdx.x * 128;
    const float* Wh = W + (size_t)h * VEC * HEAD;

    const int tid = threadIdx.x;
    const int tr  = tid >> 3;            // 0..15
    const int tc  = tid & 7;             // 0..7
    const int wr  = tid >> 2;            // 0..31  (W load row)
    const int wc  = (tid & 3) * 16;      // W load col base

    unsigned long long acc[8][4] = {};   // [i][n-pair]

    for (int kk = 0; kk < VEC; kk += 32) {
        float4 av[8], wv[4];
        #pragma unroll
        for (int u = 0; u < 8; u++)
            av[u] = *(const float4*)(A + (size_t)(r0 + tid) * VEC + kk + u * 4);
        #pragma unroll
        for (int u = 0; u < 4; u++)
            wv[u] = *(const float4*)(Wh + (size_t)(kk + wr) * HEAD + wc + u * 4);

        __syncthreads();                 // previous tile fully consumed
        #pragma unroll
        for (int u = 0; u < 8; u++) {    // transpose A -> As[k][m]
            As[(u * 4 + 0) * 128 + tid] = av[u].x;
            As[(u * 4 + 1) * 128 + tid] = av[u].y;
            As[(u * 4 + 2) * 128 + tid] = av[u].z;
            As[(u * 4 + 3) * 128 + tid] = av[u].w;
        }
        #pragma unroll
        for (int u = 0; u < 4; u++)
            *(float4*)&Ws[wr * 64 + wc + u * 4] = wv[u];
        __syncthreads();

        #pragma unroll 8
        for (int k = 0; k < 32; k++) {
            float4 a0 = *(const float4*)&As[k * 128 + tr * 8];
            float4 a1 = *(const float4*)&As[k * 128 + tr * 8 + 4];
            ulonglong2 w0 = *(const ulonglong2*)&Ws[k * 64 + tc * 8];
            ulonglong2 w1 = *(const ulonglong2*)&Ws[k * 64 + tc * 8 + 4];
            unsigned long long ad[8] = {dup2(a0.x), dup2(a0.y), dup2(a0.z), dup2(a0.w),
                                        dup2(a1.x), dup2(a1.y), dup2(a1.z), dup2(a1.w)};
            #pragma unroll
            for (int i = 0; i < 8; i++) {
                ffma2(acc[i][0], ad[i], w0.x);
                ffma2(acc[i][1], ad[i], w0.y);
                ffma2(acc[i][2], ad[i], w1.x);
                ffma2(acc[i][3], ad[i], w1.y);
            }
        }
    }

    #pragma unroll
    for (int i = 0; i < 8; i++) {
        float2 p0 = unpk(acc[i][0]), p1 = unpk(acc[i][1]);
        float2 p2 = unpk(acc[i][2]), p3 = unpk(acc[i][3]);
        float* cp = C + (size_t)(r0 + tr * 8 + i) * VEC + h * HEAD + tc * 8;
        *(float4*)(cp)     = make_float4(p0.x, p0.y, p1.x, p1.y);
        *(float4*)(cp + 4) = make_float4(p2.x, p2.y, p3.x, p3.y);
    }
}

// ---------------------------------------------------------------------------
// Attention, post-softmax tril mask, no max-subtraction (|s| <~ 2).
// Q tile 128 x K tile 64, 128 threads (16x8), 8x8 micro, FFMA2.
// ---------------------------------------------------------------------------
__global__ __launch_bounds__(128) void attn_kernel(const float* __restrict__ qmask,
                                                   const float* __restrict__ vmask) {
    extern __shared__ float sm[];
    float* Qs = sm;            // [d=64][i=128]  8192 (pre-scaled by 1/8)
    float* Ks = sm + 8192;     // [d=64][j=64]   4096
    float* Vs = sm + 12288;    // [j=64][d=64]   4096
    float* Ps = sm + 16384;    // [j=64][i=128]  8192

    const int qt = blockIdx.x;          // 0..15
    const int bh = blockIdx.y;          // 0..31
    const int b  = bh >> 3;
    const int h  = bh & 7;
    const int l0 = qt * 128;
    const size_t rowbase = (size_t)b * SEQ * VEC;

    const int tid = threadIdx.x;
    const int tr  = tid >> 3;           // 0..15
    const int tc  = tid & 7;            // 0..7
    const int jr  = tid >> 1;           // 0..63 (K/V load row)
    const int dh  = (tid & 1) * 32;     // K/V load col half

    // Q tile -> Qs[d][i], pre-scaled (visible after first in-loop syncs)
    {
        const float* qp = g_Q + rowbase + (size_t)(l0 + tid) * VEC + h * HEAD;
        #pragma unroll
        for (int u = 0; u < 16; u++) {
            float4 v = *(const float4*)(qp + u * 4);
            Qs[(u * 4 + 0) * 128 + tid] = v.x * SCALE;
            Qs[(u * 4 + 1) * 128 + tid] = v.y * SCALE;
            Qs[(u * 4 + 2) * 128 + tid] = v.z * SCALE;
            Qs[(u * 4 + 3) * 128 + tid] = v.w * SCALE;
        }
    }

    unsigned long long oacc[8][4] = {};   // [i][d-pair]
    float rsum[8] = {0.f, 0.f, 0.f, 0.f, 0.f, 0.f, 0.f, 0.f};

    for (int kt = 0; kt < 32; kt++) {
        const int k0 = kt * 64;
        const bool active  = (kt <= 2 * qt + 1);
        const bool do_mask = active && (kt >= 2 * qt);

        float4 kst[8], vst[8];
        {
            const float* kp = g_K + rowbase + (size_t)(k0 + jr) * VEC + h * HEAD + dh;
            const float* vp = g_V + rowbase + (size_t)(k0 + jr) * VEC + h * HEAD + dh;
            #pragma unroll
            for (int u = 0; u < 8; u++) kst[u] = *(const float4*)(kp + u * 4);
            #pragma unroll
            for (int u = 0; u < 8; u++) vst[u] = *(const float4*)(vp + u * 4);
        }

        __syncthreads();   // prior iteration's smem reads complete
        #pragma unroll
        for (int u = 0; u < 8; u++) {
            const int d0 = dh + u * 4;
            Ks[(d0 + 0) * 64 + jr] = kst[u].x;
            Ks[(d0 + 1) * 64 + jr] = kst[u].y;
            Ks[(d0 + 2) * 64 + jr] = kst[u].z;
            Ks[(d0 + 3) * 64 + jr] = kst[u].w;
            *(float4*)&Vs[jr * 64 + d0] = vst[u];
        }
        __syncthreads();   // tiles ready

        // S = Q K^T (Q pre-scaled). 8x8 per thread via FFMA2.
        unsigned long long s2[8][4] = {};
        #pragma unroll 8
        for (int d = 0; d < 64; d++) {
            float4 q0 = *(const float4*)&Qs[d * 128 + tr * 8];
            float4 q1 = *(const float4*)&Qs[d * 128 + tr * 8 + 4];
            ulonglong2 kp0 = *(const ulonglong2*)&Ks[d * 64 + tc * 8];
            ulonglong2 kp1 = *(const ulonglong2*)&Ks[d * 64 + tc * 8 + 4];
            unsigned long long qd[8] = {dup2(q0.x), dup2(q0.y), dup2(q0.z), dup2(q0.w),
                                        dup2(q1.x), dup2(q1.y), dup2(q1.z), dup2(q1.w)};
            #pragma unroll
            for (int i = 0; i < 8; i++) {
                ffma2(s2[i][0], qd[i], kp0.x);
                ffma2(s2[i][1], qd[i], kp0.y);
                ffma2(s2[i][2], qd[i], kp1.x);
                ffma2(s2[i][3], qd[i], kp1.y);
            }
        }

        // p = exp(s); accumulate full-row denominator (needs ALL tiles)
        float p[8][8];
        #pragma unroll
        for (int i = 0; i < 8; i++) {
            #pragma unroll
            for (int jp = 0; jp < 4; jp++) {
                float2 e = unpk(s2[i][jp]);
                float p0 = __expf(e.x), p1 = __expf(e.y);
                p[i][2 * jp]     = p0;
                p[i][2 * jp + 1] = p1;
                rsum[i] += p0 + p1;
            }
        }

        if (active) {
            const int jb = tc * 8;
            float vm[8];
            #pragma unroll
            for (int jj = 0; jj < 8; jj++)
                vm[jj] = vmask[b * SEQ + k0 + jb + jj];

            // masked numerator -> Ps[j][i]
            #pragma unroll
            for (int jj = 0; jj < 8; jj++) {
                const int kg = k0 + jb + jj;
                float v[8];
                #pragma unroll
                for (int i = 0; i < 8; i++) {
                    float x = p[i][jj] * vm[jj];
                    if (do_mask && kg > l0 + tr * 8 + i) x = 0.f;
                    v[i] = x;
                }
                float* pr = &Ps[(jb + jj) * 128 + tr * 8];
                *(float4*)(pr)     = make_float4(v[0], v[1], v[2], v[3]);
                *(float4*)(pr + 4) = make_float4(v[4], v[5], v[6], v[7]);
            }
            __syncthreads();   // Ps ready

            // O += P @ V  (8x8 per thread via FFMA2)
            #pragma unroll 8
            for (int j = 0; j < 64; j++) {
                float4 p0 = *(const float4*)&Ps[j * 128 + tr * 8];
                float4 p1 = *(const float4*)&Ps[j * 128 + tr * 8 + 4];
                ulonglong2 v0 = *(const ulonglong2*)&Vs[j * 64 + tc * 8];
                ulonglong2 v1 = *(const ulonglong2*)&Vs[j * 64 + tc * 8 + 4];
                unsigned long long pd[8] = {dup2(p0.x), dup2(p0.y), dup2(p0.z), dup2(p0.w),
                                            dup2(p1.x), dup2(p1.y), dup2(p1.z), dup2(p1.w)};
                #pragma unroll
                for (int i = 0; i < 8; i++) {
                    ffma2(oacc[i][0], pd[i], v0.x);
                    ffma2(oacc[i][1], pd[i], v0.y);
                    ffma2(oacc[i][2], pd[i], v1.x);
                    ffma2(oacc[i][3], pd[i], v1.y);
                }
            }
            // next iteration's top barrier protects the tiles
        }
    }

    // row-sum reduce across the 8 tc lanes of each row group
    #pragma unroll
    for (int i = 0; i < 8; i++) {
        float rs = rsum[i];
        #pragma unroll
        for (int o = 4; o >= 1; o >>= 1)
            rs += __shfl_xor_sync(0xffffffffu, rs, o, 8);
        rsum[i] = rs;
    }

    #pragma unroll
    for (int i = 0; i < 8; i++) {
        const int lg = l0 + tr * 8 + i;
        const float inv = qmask[b * SEQ + lg] / rsum[i];
        float2 a0 = unpk(oacc[i][0]), a1 = unpk(oacc[i][1]);
        float2 a2 = unpk(oacc[i][2]), a3 = unpk(oacc[i][3]);
        float* op = g_X + rowbase + (size_t)lg * VEC + h * HEAD + tc * 8;
        *(float4*)(op)     = make_float4(a0.x * inv, a0.y * inv, a1.x * inv, a1.y * inv);
        *(float4*)(op + 4) = make_float4(a2.x * inv, a2.y * inv, a3.x * inv, a3.y * inv);
    }
}

// ---------------------------------------------------------------------------
// Residual + LayerNorm over VEC=512. One block (256 thr) per row.
// ---------------------------------------------------------------------------
__global__ __launch_bounds__(256) void ln_kernel(const float* __restrict__ query,
                                                 const float* __restrict__ gamma,
                                                 const float* __restrict__ beta,
                                                 float* __restrict__ out) {
    const int row = blockIdx.x;
    const int tid = threadIdx.x;
    const float* xr = g_X + (size_t)row * VEC;
    const float* qr = query + (size_t)row * VEC;

    float y0 = xr[tid]       + qr[tid];
    float y1 = xr[tid + 256] + qr[tid + 256];

    float s  = y0 + y1;
    float ss = y0 * y0 + y1 * y1;
    #pragma unroll
    for (int o = 16; o >= 1; o >>= 1) {
        s  += __shfl_xor_sync(0xffffffffu, s,  o);
        ss += __shfl_xor_sync(0xffffffffu, ss, o);
    }

    __shared__ float rs[8], rss[8];
    if ((tid & 31) == 0) { rs[tid >> 5] = s; rss[tid >> 5] = ss; }
    __syncthreads();
    float S = 0.f, SS = 0.f;
    #pragma unroll
    for (int w = 0; w < 8; w++) { S += rs[w]; SS += rss[w]; }

    const float mean = S * (1.0f / VEC);
    const float var  = SS * (1.0f / VEC) - mean * mean;
    const float inv  = rsqrtf(var + LN_EPS);

    out[(size_t)row * VEC + tid]       = (y0 - mean) * inv * gamma[tid]       + beta[tid];
    out[(size_t)row * VEC + tid + 256] = (y1 - mean) * inv * gamma[tid + 256] + beta[tid + 256];
}

// ---------------------------------------------------------------------------
extern "C" void kernel_launch(void* const* d_in, const int* in_sizes, int n_in,
                              void* d_out, int out_size) {
    const float* query = (const float*)d_in[0];
    const float* key   = (const float*)d_in[1];
    const float* value = (const float*)d_in[2];
    const float* qmask = (const float*)d_in[3];
    const float* vmask = (const float*)d_in[4];
    const float* Wq    = (const float*)d_in[5];
    const float* Wk    = (const float*)d_in[6];
    const float* Wv    = (const float*)d_in[7];
    const float* gamma = (const float*)d_in[8];
    const float* beta  = (const float*)d_in[9];
    float* out = (float*)d_out;

    cudaFuncSetAttribute(attn_kernel, cudaFuncAttributeMaxDynamicSharedMemorySize, 98304);

    dim3 pgrid(ROWS / 128, HEADS);
    proj_kernel<<<pgrid, 128>>>(query, Wq, 0);
    proj_kernel<<<pgrid, 128>>>(key,   Wk, 1);
    proj_kernel<<<pgrid, 128>>>(value, Wv, 2);

    dim3 agrid(SEQ / 128, BATCH * HEADS);
    attn_kernel<<<agrid, 128, 98304>>>(qmask, vmask);

    ln_kernel<<<ROWS, 256>>>(query, gamma, beta, out);
}

// round 5
// speedup vs baseline: 1.0029x; 1.0029x over previous
#include <cuda_runtime.h>
#include <math.h>

#define BATCH 4
#define SEQ   2048
#define VEC   512
#define HEADS 8
#define HEAD  64
#define ROWS  (BATCH*SEQ)          // 8192
#define SCALE 0.125f               // 1/sqrt(64)
#define LN_EPS 1e-3f

// Scratch (allocation-free rule: __device__ globals)
__device__ float g_Q[ROWS*VEC];
__device__ float g_K[ROWS*VEC];
__device__ float g_V[ROWS*VEC];
__device__ float g_X[ROWS*VEC];

// ---- packed f32x2 helpers (ptxas never auto-fuses these) --------------------
__device__ __forceinline__ void ffma2(unsigned long long& d,
                                      unsigned long long a,
                                      unsigned long long b) {
    asm("fma.rn.f32x2 %0, %1, %2, %0;" : "+l"(d) : "l"(a), "l"(b));
}
__device__ __forceinline__ unsigned long long dup2(float x) {
    unsigned long long r;
    asm("mov.b64 %0, {%1, %1};" : "=l"(r) : "f"(x));
    return r;
}
__device__ __forceinline__ float2 unpk(unsigned long long p) {
    float2 f;
    asm("mov.b64 {%0, %1}, %2;" : "=f"(f.x), "=f"(f.y) : "l"(p));
    return f;
}

// ---------------------------------------------------------------------------
// Projection: C[row, h*64+d] = sum_v A[row,v] * W[h,v,d]
// BM=128, BN=64 (one head), BK=32. 128 threads (16x8), 8x8 micro, FFMA2.
// ---------------------------------------------------------------------------
__global__ __launch_bounds__(128) void proj_kernel(const float* __restrict__ A,
                                                   const float* __restrict__ W,
                                                   int sel) {
    float* C = (sel == 0) ? g_Q : (sel == 1) ? g_K : g_V;

    __shared__ float As[32 * 128];   // [k][m]
    __shared__ float Ws[32 * 64];    // [k][n]

    const int h  = blockIdx.y;
    const int r0 = blockIdx.x * 128;
    const float* Wh = W + (size_t)h * VEC * HEAD;

    const int tid = threadIdx.x;
    const int tr  = tid >> 3;            // 0..15
    const int tc  = tid & 7;             // 0..7
    const int wr  = tid >> 2;            // 0..31  (W load row)
    const int wc  = (tid & 3) * 16;      // W load col base

    unsigned long long acc[8][4] = {};   // [i][n-pair]

    for (int kk = 0; kk < VEC; kk += 32) {
        float4 av[8], wv[4];
        #pragma unroll
        for (int u = 0; u < 8; u++)
            av[u] = *(const float4*)(A + (size_t)(r0 + tid) * VEC + kk + u * 4);
        #pragma unroll
        for (int u = 0; u < 4; u++)
            wv[u] = *(const float4*)(Wh + (size_t)(kk + wr) * HEAD + wc + u * 4);

        __syncthreads();                 // previous tile fully consumed
        #pragma unroll
        for (int u = 0; u < 8; u++) {    // transpose A -> As[k][m]
            As[(u * 4 + 0) * 128 + tid] = av[u].x;
            As[(u * 4 + 1) * 128 + tid] = av[u].y;
            As[(u * 4 + 2) * 128 + tid] = av[u].z;
            As[(u * 4 + 3) * 128 + tid] = av[u].w;
        }
        #pragma unroll
        for (int u = 0; u < 4; u++)
            *(float4*)&Ws[wr * 64 + wc + u * 4] = wv[u];
        __syncthreads();

        #pragma unroll 8
        for (int k = 0; k < 32; k++) {
            float4 a0 = *(const float4*)&As[k * 128 + tr * 8];
            float4 a1 = *(const float4*)&As[k * 128 + tr * 8 + 4];
            ulonglong2 w0 = *(const ulonglong2*)&Ws[k * 64 + tc * 8];
            ulonglong2 w1 = *(const ulonglong2*)&Ws[k * 64 + tc * 8 + 4];
            unsigned long long ad[8] = {dup2(a0.x), dup2(a0.y), dup2(a0.z), dup2(a0.w),
                                        dup2(a1.x), dup2(a1.y), dup2(a1.z), dup2(a1.w)};
            #pragma unroll
            for (int i = 0; i < 8; i++) {
                ffma2(acc[i][0], ad[i], w0.x);
                ffma2(acc[i][1], ad[i], w0.y);
                ffma2(acc[i][2], ad[i], w1.x);
                ffma2(acc[i][3], ad[i], w1.y);
            }
        }
    }

    #pragma unroll
    for (int i = 0; i < 8; i++) {
        float2 p0 = unpk(acc[i][0]), p1 = unpk(acc[i][1]);
        float2 p2 = unpk(acc[i][2]), p3 = unpk(acc[i][3]);
        float* cp = C + (size_t)(r0 + tr * 8 + i) * VEC + h * HEAD + tc * 8;
        *(float4*)(cp)     = make_float4(p0.x, p0.y, p1.x, p1.y);
        *(float4*)(cp + 4) = make_float4(p2.x, p2.y, p3.x, p3.y);
    }
}

// ---------------------------------------------------------------------------
// Attention, post-softmax tril mask, no max-subtraction (|s| <~ 2).
// Q tile 128 x K tile 64, 128 threads (16x8), 8x8 micro, FFMA2.
// ---------------------------------------------------------------------------
__global__ __launch_bounds__(128) void attn_kernel(const float* __restrict__ qmask,
                                                   const float* __restrict__ vmask) {
    extern __shared__ float sm[];
    float* Qs = sm;            // [d=64][i=128]  8192 (pre-scaled by 1/8)
    float* Ks = sm + 8192;     // [d=64][j=64]   4096
    float* Vs = sm + 12288;    // [j=64][d=64]   4096
    float* Ps = sm + 16384;    // [j=64][i=128]  8192

    const int qt = blockIdx.x;          // 0..15
    const int bh = blockIdx.y;          // 0..31
    const int b  = bh >> 3;
    const int h  = bh & 7;
    const int l0 = qt * 128;
    const size_t rowbase = (size_t)b * SEQ * VEC;

    const int tid = threadIdx.x;
    const int tr  = tid >> 3;           // 0..15
    const int tc  = tid & 7;            // 0..7
    const int jr  = tid >> 1;           // 0..63 (K/V load row)
    const int dh  = (tid & 1) * 32;     // K/V load col half

    // Q tile -> Qs[d][i], pre-scaled (visible after first in-loop syncs)
    {
        const float* qp = g_Q + rowbase + (size_t)(l0 + tid) * VEC + h * HEAD;
        #pragma unroll
        for (int u = 0; u < 16; u++) {
            float4 v = *(const float4*)(qp + u * 4);
            Qs[(u * 4 + 0) * 128 + tid] = v.x * SCALE;
            Qs[(u * 4 + 1) * 128 + tid] = v.y * SCALE;
            Qs[(u * 4 + 2) * 128 + tid] = v.z * SCALE;
            Qs[(u * 4 + 3) * 128 + tid] = v.w * SCALE;
        }
    }

    unsigned long long oacc[8][4] = {};   // [i][d-pair]
    float rsum[8] = {0.f, 0.f, 0.f, 0.f, 0.f, 0.f, 0.f, 0.f};

    for (int kt = 0; kt < 32; kt++) {
        const int k0 = kt * 64;
        const bool active  = (kt <= 2 * qt + 1);
        const bool do_mask = active && (kt >= 2 * qt);

        float4 kst[8], vst[8];
        {
            const float* kp = g_K + rowbase + (size_t)(k0 + jr) * VEC + h * HEAD + dh;
            const float* vp = g_V + rowbase + (size_t)(k0 + jr) * VEC + h * HEAD + dh;
            #pragma unroll
            for (int u = 0; u < 8; u++) kst[u] = *(const float4*)(kp + u * 4);
            #pragma unroll
            for (int u = 0; u < 8; u++) vst[u] = *(const float4*)(vp + u * 4);
        }

        __syncthreads();   // prior iteration's smem reads complete
        #pragma unroll
        for (int u = 0; u < 8; u++) {
            const int d0 = dh + u * 4;
            Ks[(d0 + 0) * 64 + jr] = kst[u].x;
            Ks[(d0 + 1) * 64 + jr] = kst[u].y;
            Ks[(d0 + 2) * 64 + jr] = kst[u].z;
            Ks[(d0 + 3) * 64 + jr] = kst[u].w;
            *(float4*)&Vs[jr * 64 + d0] = vst[u];
        }
        __syncthreads();   // tiles ready

        // S = Q K^T (Q pre-scaled). 8x8 per thread via FFMA2.
        unsigned long long s2[8][4] = {};
        #pragma unroll 8
        for (int d = 0; d < 64; d++) {
            float4 q0 = *(const float4*)&Qs[d * 128 + tr * 8];
            float4 q1 = *(const float4*)&Qs[d * 128 + tr * 8 + 4];
            ulonglong2 kp0 = *(const ulonglong2*)&Ks[d * 64 + tc * 8];
            ulonglong2 kp1 = *(const ulonglong2*)&Ks[d * 64 + tc * 8 + 4];
            unsigned long long qd[8] = {dup2(q0.x), dup2(q0.y), dup2(q0.z), dup2(q0.w),
                                        dup2(q1.x), dup2(q1.y), dup2(q1.z), dup2(q1.w)};
            #pragma unroll
            for (int i = 0; i < 8; i++) {
                ffma2(s2[i][0], qd[i], kp0.x);
                ffma2(s2[i][1], qd[i], kp0.y);
                ffma2(s2[i][2], qd[i], kp1.x);
                ffma2(s2[i][3], qd[i], kp1.y);
            }
        }

        // p = exp(s); accumulate full-row denominator (needs ALL tiles)
        float p[8][8];
        #pragma unroll
        for (int i = 0; i < 8; i++) {
            #pragma unroll
            for (int jp = 0; jp < 4; jp++) {
                float2 e = unpk(s2[i][jp]);
                float p0 = __expf(e.x), p1 = __expf(e.y);
                p[i][2 * jp]     = p0;
                p[i][2 * jp + 1] = p1;
                rsum[i] += p0 + p1;
            }
        }

        if (active) {
            const int jb = tc * 8;
            float vm[8];
            #pragma unroll
            for (int jj = 0; jj < 8; jj++)
                vm[jj] = vmask[b * SEQ + k0 + jb + jj];

            // masked numerator -> Ps[j][i]
            #pragma unroll
            for (int jj = 0; jj < 8; jj++) {
                const int kg = k0 + jb + jj;
                float v[8];
                #pragma unroll
                for (int i = 0; i < 8; i++) {
                    float x = p[i][jj] * vm[jj];
                    if (do_mask && kg > l0 + tr * 8 + i) x = 0.f;
                    v[i] = x;
                }
                float* pr = &Ps[(jb + jj) * 128 + tr * 8];
                *(float4*)(pr)     = make_float4(v[0], v[1], v[2], v[3]);
                *(float4*)(pr + 4) = make_float4(v[4], v[5], v[6], v[7]);
            }
            __syncthreads();   // Ps ready

            // O += P @ V  (8x8 per thread via FFMA2)
            #pragma unroll 8
            for (int j = 0; j < 64; j++) {
                float4 p0 = *(const float4*)&Ps[j * 128 + tr * 8];
                float4 p1 = *(const float4*)&Ps[j * 128 + tr * 8 + 4];
                ulonglong2 v0 = *(const ulonglong2*)&Vs[j * 64 + tc * 8];
                ulonglong2 v1 = *(const ulonglong2*)&Vs[j * 64 + tc * 8 + 4];
                unsigned long long pd[8] = {dup2(p0.x), dup2(p0.y), dup2(p0.z), dup2(p0.w),
                                            dup2(p1.x), dup2(p1.y), dup2(p1.z), dup2(p1.w)};
                #pragma unroll
                for (int i = 0; i < 8; i++) {
                    ffma2(oacc[i][0], pd[i], v0.x);
                    ffma2(oacc[i][1], pd[i], v0.y);
                    ffma2(oacc[i][2], pd[i], v1.x);
                    ffma2(oacc[i][3], pd[i], v1.y);
                }
            }
            // next iteration's top barrier protects the tiles
        }
    }

    // row-sum reduce across the 8 tc lanes of each row group
    #pragma unroll
    for (int i = 0; i < 8; i++) {
        float rs = rsum[i];
        #pragma unroll
        for (int o = 4; o >= 1; o >>= 1)
            rs += __shfl_xor_sync(0xffffffffu, rs, o, 8);
        rsum[i] = rs;
    }

    #pragma unroll
    for (int i = 0; i < 8; i++) {
        const int lg = l0 + tr * 8 + i;
        const float inv = qmask[b * SEQ + lg] / rsum[i];
        float2 a0 = unpk(oacc[i][0]), a1 = unpk(oacc[i][1]);
        float2 a2 = unpk(oacc[i][2]), a3 = unpk(oacc[i][3]);
        float* op = g_X + rowbase + (size_t)lg * VEC + h * HEAD + tc * 8;
        *(float4*)(op)     = make_float4(a0.x * inv, a0.y * inv, a1.x * inv, a1.y * inv);
        *(float4*)(op + 4) = make_float4(a2.x * inv, a2.y * inv, a3.x * inv, a3.y * inv);
    }
}

// ---------------------------------------------------------------------------
// Residual + LayerNorm over VEC=512. One block (256 thr) per row.
// ---------------------------------------------------------------------------
__global__ __launch_bounds__(256) void ln_kernel(const float* __restrict__ query,
                                                 const float* __restrict__ gamma,
                                                 const float* __restrict__ beta,
                                                 float* __restrict__ out) {
    const int row = blockIdx.x;
    const int tid = threadIdx.x;
    const float* xr = g_X + (size_t)row * VEC;
    const float* qr = query + (size_t)row * VEC;

    float y0 = xr[tid]       + qr[tid];
    float y1 = xr[tid + 256] + qr[tid + 256];

    float s  = y0 + y1;
    float ss = y0 * y0 + y1 * y1;
    #pragma unroll
    for (int o = 16; o >= 1; o >>= 1) {
        s  += __shfl_xor_sync(0xffffffffu, s,  o);
        ss += __shfl_xor_sync(0xffffffffu, ss, o);
    }

    __shared__ float rs[8], rss[8];
    if ((tid & 31) == 0) { rs[tid >> 5] = s; rss[tid >> 5] = ss; }
    __syncthreads();
    float S = 0.f, SS = 0.f;
    #pragma unroll
    for (int w = 0; w < 8; w++) { S += rs[w]; SS += rss[w]; }

    const float mean = S * (1.0f / VEC);
    const float var  = SS * (1.0f / VEC) - mean * mean;
    const float inv  = rsqrtf(var + LN_EPS);

    out[(size_t)row * VEC + tid]       = (y0 - mean) * inv * gamma[tid]       + beta[tid];
    out[(size_t)row * VEC + tid + 256] = (y1 - mean) * inv * gamma[tid + 256] + beta[tid + 256];
}

// ---------------------------------------------------------------------------
extern "C" void kernel_launch(void* const* d_in, const int* in_sizes, int n_in,
                              void* d_out, int out_size) {
    const float* query = (const float*)d_in[0];
    const float* key   = (const float*)d_in[1];
    const float* value = (const float*)d_in[2];
    const float* qmask = (const float*)d_in[3];
    const float* vmask = (const float*)d_in[4];
    const float* Wq    = (const float*)d_in[5];
    const float* Wk    = (const float*)d_in[6];
    const float* Wv    = (const float*)d_in[7];
    const float* gamma = (const float*)d_in[8];
    const float* beta  = (const float*)d_in[9];
    float* out = (float*)d_out;

    cudaFuncSetAttribute(attn_kernel, cudaFuncAttributeMaxDynamicSharedMemorySize, 98304);

    dim3 pgrid(ROWS / 128, HEADS);
    proj_kernel<<<pgrid, 128>>>(query, Wq, 0);
    proj_kernel<<<pgrid, 128>>>(key,   Wk, 1);
    proj_kernel<<<pgrid, 128>>>(value, Wv, 2);

    dim3 agrid(SEQ / 128, BATCH * HEADS);
    attn_kernel<<<agrid, 128, 98304>>>(qmask, vmask);

    ln_kernel<<<ROWS, 256>>>(query, gamma, beta, out);
}

// round 6
// speedup vs baseline: 2.4856x; 2.4784x over previous
#include <cuda_runtime.h>
#include <math.h>

#define BATCH 4
#define SEQ   2048
#define VEC   512
#define HEADS 8
#define HEAD  64
#define ROWS  (BATCH*SEQ)          // 8192
#define SCALE 0.125f               // 1/sqrt(64)
#define LN_EPS 1e-3f

// Scratch (allocation-free rule: __device__ globals)
__device__ float g_Q[ROWS*VEC];
__device__ float g_K[ROWS*VEC];
__device__ float g_V[ROWS*VEC];
__device__ float g_X[ROWS*VEC];

// ---- tf32 helpers -----------------------------------------------------------
__device__ __forceinline__ unsigned f2tf(float x) {
    unsigned r;
    asm("cvt.rna.tf32.f32 %0, %1;" : "=r"(r) : "f"(x));
    return r;
}
// D += A(16x8,row) * B(8x8,col) ; tf32 inputs, f32 accum
__device__ __forceinline__ void mma8(float c[4], const unsigned a[4], const unsigned b[2]) {
    asm("mma.sync.aligned.m16n8k8.row.col.f32.tf32.tf32.f32 "
        "{%0,%1,%2,%3}, {%4,%5,%6,%7}, {%8,%9}, {%0,%1,%2,%3};"
        : "+f"(c[0]), "+f"(c[1]), "+f"(c[2]), "+f"(c[3])
        : "r"(a[0]), "r"(a[1]), "r"(a[2]), "r"(a[3]), "r"(b[0]), "r"(b[1]));
}

// ---------------------------------------------------------------------------
// Projection (tf32 tensor): C[row, h*64+d] = sum_v A[row,v] * W[h,v,d]
// Block: 256 thr / 8 warps. Tile M=128 (16 rows/warp), N=64 (one head), BK=32.
// ---------------------------------------------------------------------------
__global__ __launch_bounds__(256) void proj_kernel(const float* __restrict__ A,
                                                   const float* __restrict__ W,
                                                   int sel) {
    float* C = (sel == 0) ? g_Q : (sel == 1) ? g_K : g_V;

    __shared__ unsigned As[128 * 36];   // [m][k], stride 36 (banks 4g+tg)
    __shared__ unsigned Ws[32 * 72];    // [k=v][n=d], stride 72 (banks 8tg+g)

    const int h  = blockIdx.y;
    const int r0 = blockIdx.x * 128;
    const float* Wh = W + (size_t)h * VEC * HEAD;

    const int tid  = threadIdx.x;
    const int w    = tid >> 5;
    const int lane = tid & 31;
    const int g    = lane >> 2;        // 0..7
    const int tg   = lane & 3;         // 0..3

    float acc[8][4] = {};              // [n-block][frag]

    for (int kk = 0; kk < VEC; kk += 32) {
        __syncthreads();               // previous chunk fully consumed
        // A chunk 128x32 -> As (tf32)
        {
            const int r  = tid >> 1;
            const int cb = (tid & 1) * 16;
            const float* ap = A + (size_t)(r0 + r) * VEC + kk + cb;
            #pragma unroll
            for (int u = 0; u < 4; u++) {
                float4 v = *(const float4*)(ap + u * 4);
                unsigned* d = &As[r * 36 + cb + u * 4];
                d[0] = f2tf(v.x); d[1] = f2tf(v.y); d[2] = f2tf(v.z); d[3] = f2tf(v.w);
            }
        }
        // W chunk 32x64 -> Ws (tf32)
        {
            const int r  = tid >> 3;
            const int cb = (tid & 7) * 8;
            const float* wp = Wh + (size_t)(kk + r) * HEAD + cb;
            #pragma unroll
            for (int u = 0; u < 2; u++) {
                float4 v = *(const float4*)(wp + u * 4);
                unsigned* d = &Ws[r * 72 + cb + u * 4];
                d[0] = f2tf(v.x); d[1] = f2tf(v.y); d[2] = f2tf(v.z); d[3] = f2tf(v.w);
            }
        }
        __syncthreads();

        #pragma unroll
        for (int ks = 0; ks < 4; ks++) {
            unsigned a[4];
            const unsigned* ap = &As[(w * 16 + g) * 36 + ks * 8 + tg];
            a[0] = ap[0];
            a[1] = ap[8 * 36];
            a[2] = ap[4];
            a[3] = ap[8 * 36 + 4];
            #pragma unroll
            for (int nb = 0; nb < 8; nb++) {
                unsigned b[2];
                b[0] = Ws[(ks * 8 + tg) * 72 + nb * 8 + g];
                b[1] = Ws[(ks * 8 + tg + 4) * 72 + nb * 8 + g];
                mma8(acc[nb], a, b);
            }
        }
    }

    // epilogue: c0/c1 -> row g, cols 2tg,2tg+1 ; c2/c3 -> row g+8
    const int rA = r0 + w * 16 + g;
    #pragma unroll
    for (int nb = 0; nb < 8; nb++) {
        const int col = h * HEAD + nb * 8 + 2 * tg;
        *(float2*)(C + (size_t)rA * VEC + col)       = make_float2(acc[nb][0], acc[nb][1]);
        *(float2*)(C + (size_t)(rA + 8) * VEC + col) = make_float2(acc[nb][2], acc[nb][3]);
    }
}

// ---------------------------------------------------------------------------
// Attention (tf32 tensor). Post-softmax tril mask; denominator over ALL keys
// (no max-subtraction: |s| <~ 2, validated in prior rounds).
// Block: 256 thr / 8 warps. Q tile 128 rows (16/warp), K tile 64.
// vmask folded into V rows at load; qmask applied at epilogue.
// ---------------------------------------------------------------------------
__global__ __launch_bounds__(256, 2) void attn_kernel(const float* __restrict__ qmask,
                                                      const float* __restrict__ vmask) {
    extern __shared__ unsigned sm[];
    unsigned* Qs = sm;                         // [128][68] tf32, pre-scaled
    unsigned* Ks = Qs + 128 * 68;              // [j=64][d][stride 68]
    unsigned* Vs = Ks + 64 * 68;               // [j=64][d][stride 72], vmask-folded
    unsigned* Ps = Vs + 64 * 72;               // per-warp [16][68]

    const int qt = (int)gridDim.x - 1 - (int)blockIdx.x;   // heavy blocks first
    const int bh = blockIdx.y;
    const int b  = bh >> 3;
    const int h  = bh & 7;
    const int l0 = qt * 128;
    const size_t rowbase = (size_t)b * SEQ * VEC;

    const int tid  = threadIdx.x;
    const int w    = tid >> 5;
    const int lane = tid & 31;
    const int g    = lane >> 2;
    const int tg   = lane & 3;

    // Q tile -> Qs (scaled, tf32). 128x64, 32 elems/thread.
    {
        const int r  = tid >> 1;
        const int cb = (tid & 1) * 32;
        const float* qp = g_Q + rowbase + (size_t)(l0 + r) * VEC + h * HEAD + cb;
        #pragma unroll
        for (int u = 0; u < 8; u++) {
            float4 v = *(const float4*)(qp + u * 4);
            unsigned* d = &Qs[r * 68 + cb + u * 4];
            d[0] = f2tf(v.x * SCALE); d[1] = f2tf(v.y * SCALE);
            d[2] = f2tf(v.z * SCALE); d[3] = f2tf(v.w * SCALE);
        }
    }

    unsigned* Pw = Ps + w * 16 * 68;
    float oacc[8][4] = {};
    float rsum0 = 0.f, rsum1 = 0.f;    // rows g and g+8 of this warp's 16

    const int lgA = l0 + w * 16 + g;
    const int lgB = lgA + 8;

    for (int kt = 0; kt < 32; kt++) {
        const int k0 = kt * 64;
        const bool active  = (kt <= 2 * qt + 1);
        const bool do_mask = active && (kt >= 2 * qt);

        __syncthreads();   // prior iteration's Ks/Vs reads complete
        // K,V tiles -> smem (tf32; V scaled by vmask row)
        {
            const int jr = tid >> 2;
            const int cb = (tid & 3) * 16;
            const float* kp = g_K + rowbase + (size_t)(k0 + jr) * VEC + h * HEAD + cb;
            const float* vp = g_V + rowbase + (size_t)(k0 + jr) * VEC + h * HEAD + cb;
            const float vmr = vmask[b * SEQ + k0 + jr];
            #pragma unroll
            for (int u = 0; u < 4; u++) {
                float4 kv = *(const float4*)(kp + u * 4);
                unsigned* kd = &Ks[jr * 68 + cb + u * 4];
                kd[0] = f2tf(kv.x); kd[1] = f2tf(kv.y); kd[2] = f2tf(kv.z); kd[3] = f2tf(kv.w);
                float4 vv = *(const float4*)(vp + u * 4);
                unsigned* vd = &Vs[jr * 72 + cb + u * 4];
                vd[0] = f2tf(vv.x * vmr); vd[1] = f2tf(vv.y * vmr);
                vd[2] = f2tf(vv.z * vmr); vd[3] = f2tf(vv.w * vmr);
            }
        }
        __syncthreads();

        // S = Q K^T  (16x64 per warp), always (denominator needs all tiles)
        float sacc[8][4] = {};
        #pragma unroll
        for (int ks = 0; ks < 8; ks++) {
            unsigned a[4];
            const unsigned* ap = &Qs[(w * 16 + g) * 68 + ks * 8 + tg];
            a[0] = ap[0];
            a[1] = ap[8 * 68];
            a[2] = ap[4];
            a[3] = ap[8 * 68 + 4];
            #pragma unroll
            for (int nb = 0; nb < 8; nb++) {
                unsigned bfr[2];
                bfr[0] = Ks[(nb * 8 + g) * 68 + ks * 8 + tg];
                bfr[1] = Ks[(nb * 8 + g) * 68 + ks * 8 + tg + 4];
                mma8(sacc[nb], a, bfr);
            }
        }

        // exp (always, into sacc) + rsum; then masked P -> Ps if active
        #pragma unroll
        for (int nb = 0; nb < 8; nb++) {
            float p0 = __expf(sacc[nb][0]);
            float p1 = __expf(sacc[nb][1]);
            float p2 = __expf(sacc[nb][2]);
            float p3 = __expf(sacc[nb][3]);
            rsum0 += p0 + p1;
            rsum1 += p2 + p3;
            sacc[nb][0] = p0; sacc[nb][1] = p1; sacc[nb][2] = p2; sacc[nb][3] = p3;
        }

        if (active) {
            __syncwarp();   // prior PV reads of Pw complete (WAR)
            #pragma unroll
            for (int nb = 0; nb < 8; nb++) {
                const int c0 = nb * 8 + 2 * tg;
                const int kg = k0 + c0;
                float p0 = sacc[nb][0], p1 = sacc[nb][1];
                float p2 = sacc[nb][2], p3 = sacc[nb][3];
                if (do_mask) {
                    if (kg > lgA)     p0 = 0.f;
                    if (kg + 1 > lgA) p1 = 0.f;
                    if (kg > lgB)     p2 = 0.f;
                    if (kg + 1 > lgB) p3 = 0.f;
                }
                Pw[g * 68 + c0]           = f2tf(p0);
                Pw[g * 68 + c0 + 1]       = f2tf(p1);
                Pw[(g + 8) * 68 + c0]     = f2tf(p2);
                Pw[(g + 8) * 68 + c0 + 1] = f2tf(p3);
            }
            __syncwarp();

            // O += P @ V   (k = j dimension)
            #pragma unroll
            for (int ks = 0; ks < 8; ks++) {
                unsigned a[4];
                const unsigned* ap = &Pw[g * 68 + ks * 8 + tg];
                a[0] = ap[0];
                a[1] = ap[8 * 68];
                a[2] = ap[4];
                a[3] = ap[8 * 68 + 4];
                #pragma unroll
                for (int nb = 0; nb < 8; nb++) {
                    unsigned bfr[2];
                    bfr[0] = Vs[(ks * 8 + tg) * 72 + nb * 8 + g];
                    bfr[1] = Vs[(ks * 8 + tg + 4) * 72 + nb * 8 + g];
                    mma8(oacc[nb], a, bfr);
                }
            }
        }
    }

    // finalize row sums: reduce over the 4 lanes of each quad (cols tg)
    rsum0 += __shfl_xor_sync(0xffffffffu, rsum0, 1);
    rsum0 += __shfl_xor_sync(0xffffffffu, rsum0, 2);
    rsum1 += __shfl_xor_sync(0xffffffffu, rsum1, 1);
    rsum1 += __shfl_xor_sync(0xffffffffu, rsum1, 2);

    const float invA = qmask[b * SEQ + lgA] / rsum0;
    const float invB = qmask[b * SEQ + lgB] / rsum1;

    #pragma unroll
    for (int nb = 0; nb < 8; nb++) {
        const int col = h * HEAD + nb * 8 + 2 * tg;
        *(float2*)(g_X + rowbase + (size_t)lgA * VEC + col) =
            make_float2(oacc[nb][0] * invA, oacc[nb][1] * invA);
        *(float2*)(g_X + rowbase + (size_t)lgB * VEC + col) =
            make_float2(oacc[nb][2] * invB, oacc[nb][3] * invB);
    }
}

// ---------------------------------------------------------------------------
// Residual + LayerNorm over VEC=512. One block (256 thr) per row.
// ---------------------------------------------------------------------------
__global__ __launch_bounds__(256) void ln_kernel(const float* __restrict__ query,
                                                 const float* __restrict__ gamma,
                                                 const float* __restrict__ beta,
                                                 float* __restrict__ out) {
    const int row = blockIdx.x;
    const int tid = threadIdx.x;
    const float* xr = g_X + (size_t)row * VEC;
    const float* qr = query + (size_t)row * VEC;

    float y0 = xr[tid]       + qr[tid];
    float y1 = xr[tid + 256] + qr[tid + 256];

    float s  = y0 + y1;
    float ss = y0 * y0 + y1 * y1;
    #pragma unroll
    for (int o = 16; o >= 1; o >>= 1) {
        s  += __shfl_xor_sync(0xffffffffu, s,  o);
        ss += __shfl_xor_sync(0xffffffffu, ss, o);
    }

    __shared__ float rs[8], rss[8];
    if ((tid & 31) == 0) { rs[tid >> 5] = s; rss[tid >> 5] = ss; }
    __syncthreads();
    float S = 0.f, SS = 0.f;
    #pragma unroll
    for (int w = 0; w < 8; w++) { S += rs[w]; SS += rss[w]; }

    const float mean = S * (1.0f / VEC);
    const float var  = SS * (1.0f / VEC) - mean * mean;
    const float inv  = rsqrtf(var + LN_EPS);

    out[(size_t)row * VEC + tid]       = (y0 - mean) * inv * gamma[tid]       + beta[tid];
    out[(size_t)row * VEC + tid + 256] = (y1 - mean) * inv * gamma[tid + 256] + beta[tid + 256];
}

// ---------------------------------------------------------------------------
extern "C" void kernel_launch(void* const* d_in, const int* in_sizes, int n_in,
                              void* d_out, int out_size) {
    const float* query = (const float*)d_in[0];
    const float* key   = (const float*)d_in[1];
    const float* value = (const float*)d_in[2];
    const float* qmask = (const float*)d_in[3];
    const float* vmask = (const float*)d_in[4];
    const float* Wq    = (const float*)d_in[5];
    const float* Wk    = (const float*)d_in[6];
    const float* Wv    = (const float*)d_in[7];
    const float* gamma = (const float*)d_in[8];
    const float* beta  = (const float*)d_in[9];
    float* out = (float*)d_out;

    const int ATTN_SMEM = (128 * 68 + 64 * 68 + 64 * 72 + 8 * 16 * 68) * 4;  // 105472
    cudaFuncSetAttribute(attn_kernel, cudaFuncAttributeMaxDynamicSharedMemorySize, ATTN_SMEM);

    dim3 pgrid(ROWS / 128, HEADS);
    proj_kernel<<<pgrid, 256>>>(query, Wq, 0);
    proj_kernel<<<pgrid, 256>>>(key,   Wk, 1);
    proj_kernel<<<pgrid, 256>>>(value, Wv, 2);

    dim3 agrid(SEQ / 128, BATCH * HEADS);
    attn_kernel<<<agrid, 256, ATTN_SMEM>>>(qmask, vmask);

    ln_kernel<<<ROWS, 256>>>(query, gamma, beta, out);
}